// round 16
// baseline (speedup 1.0000x reference)
#include <cuda_runtime.h>
#include <cuda_fp16.h>
#include <cstdint>

// ============================================================================
// DGM cell fused kernel for plain sm_103 (no tcgen05 on this ptxas target).
// mma.sync.m16n8k16 (HMMA) + ldmatrix + cp.async.bulk.
// B=262144, D_IN=8, H=128, N_LAYERS=3, D_OUT=1.
//
// R16 = R14 (339.9us best; R15's atomic-counter recycling regressed and is
// reverted) + PERSISTENT CTAs:
//  * Grid 296 (=148 SMs x 2), each CTA loops ~14 row-tiles of 64 rows.
//  * Ring state is tile-periodic (12 gates = 6 uses/slot: slot=G&1 and both
//    mbarrier parities return to phase every tile) -> inner gate loop is
//    identical to R14; refill source is (t*12+G+2)%12, bound 12*T.
//  * Kills 13 CLC wave transitions + amortizes per-CTA init and the
//    first-gate load exposure (once per CTA, not once per 64-row tile).
//
// CTA: 64 rows/tile, 256 threads (8 warps). Warp w: rows m0=(w&1)*32,
// cols n0=(w>>1)*32. acc = 2x4 m16n8 tiles (32 fp32 regs).
// A tile (SMEM): [64 rows][152 halves]: sigS 0..127, x 128..135, 1 @136,
// 0 @137..143. Gate = one K=144 MMA chain (x@U + bias folded in).
// B images: [144][136] fp16 per gate, 2-slot ring, prefetch depth 2,
// consumed-mbarrier recycling (R14), m-group named barriers, slimmed
// critical sections (R14), broadcast S0 prologue (R13), f16x2 acts (R8/R11).
// ============================================================================

#define GATE_HALVES (144 * 136)
#define GATE_BYTES  39168u
#define IMG_TOTAL   (12u * GATE_BYTES)
#define NCTA        296
#define NTILES      4096

__device__ __align__(1024) unsigned char g_wimg[IMG_TOTAL];

// ---------------- smem layout (bytes) ----------------
#define OFF_MBAR  0u        // 2 full mbarriers
#define OFF_CONS  16u       // 2 consumed mbarriers
#define OFF_OUTS  64u       // 64 f32
#define OFF_WF    320u      // 129 f32 (Wf + bias)
#define OFF_SW    896u      // 8*128 f32
#define OFF_SWB   4992u     // 128 f32
#define OFF_A     5504u     // 64*304 B = 19456 (stride 152 halves)
#define OFF_SLOT0 25600u    // 39168
#define OFF_SLOT1 64768u    // 39168
#define SMEM_TOTAL 103936u

// ---------------- PTX helpers ----------------
__device__ __forceinline__ uint32_t smem_to_u32(const void* p) {
    uint32_t a;
    asm("{ .reg .u64 t; cvta.to.shared.u64 t, %1; cvt.u32.u64 %0, t; }" : "=r"(a) : "l"(p));
    return a;
}

#define MBARRIER_INIT(addr, cnt) \
    asm volatile("mbarrier.init.shared.b64 [%0], %1;" :: "r"((uint32_t)(addr)), "r"((uint32_t)(cnt)) : "memory")

#define MBARRIER_EXPECT_TX(addr, bytes) \
    asm volatile("mbarrier.arrive.expect_tx.shared.b64 _, [%0], %1;" \
        :: "r"((uint32_t)(addr)), "r"((uint32_t)(bytes)) : "memory")

#define MBARRIER_ARRIVE(addr) \
    asm volatile("mbarrier.arrive.shared.b64 _, [%0];" :: "r"((uint32_t)(addr)) : "memory")

#define MBARRIER_WAIT_PARITY(mbar_smem_addr, phase_parity) do { \
    uint32_t _mbar = (uint32_t)(mbar_smem_addr); \
    uint32_t _parity = (uint32_t)(phase_parity); \
    uint32_t _done; \
    asm volatile("{\n\t.reg .pred p;\n\t" \
        "mbarrier.try_wait.parity.acquire.cta.shared::cta.b64 p, [%1], %2;\n\t" \
        "selp.b32 %0, 1, 0, p;\n\t}" \
        : "=r"(_done) : "r"(_mbar), "r"(_parity) : "memory"); \
    if (!_done) { \
        asm volatile("{\n\t.reg .pred P1;\n\t" \
            "WAIT_LOOP_%=:\n\t" \
            "mbarrier.try_wait.parity.acquire.cta.shared::cta.b64 P1, [%0], %1, 0x989680;\n\t" \
            "@P1 bra.uni WAIT_DONE_%=;\n\t" \
            "bra.uni WAIT_LOOP_%=;\n\t" \
            "WAIT_DONE_%=:\n\t}" \
            :: "r"(_mbar), "r"(_parity) : "memory"); \
    } \
} while(0)

__device__ __forceinline__ void mbarrier_inval(uint32_t a) {
    asm volatile("mbarrier.inval.shared.b64 [%0];" :: "r"(a) : "memory");
}

__device__ __forceinline__ void bulk_g2s(uint32_t dst, const void* src,
                                         uint32_t bytes, uint32_t mbar) {
    asm volatile(
        "cp.async.bulk.shared::cluster.global.mbarrier::complete_tx::bytes "
        "[%0], [%1], %2, [%3];"
        :: "r"(dst), "l"(src), "r"(bytes), "r"(mbar) : "memory");
}

// half-CTA barrier for one m-group (4 warps = 128 threads), ids 1 and 2
#define GROUP_BAR(grp) \
    asm volatile("bar.sync %0, %1;" :: "r"((grp) + 1), "r"(128) : "memory")

__device__ __forceinline__ void ldsm4(uint32_t* r, uint32_t a) {
    asm volatile("ldmatrix.sync.aligned.m8n8.x4.shared.b16 {%0,%1,%2,%3}, [%4];"
        : "=r"(r[0]), "=r"(r[1]), "=r"(r[2]), "=r"(r[3]) : "r"(a));
}
__device__ __forceinline__ void ldsm4t(uint32_t* r, uint32_t a) {
    asm volatile("ldmatrix.sync.aligned.m8n8.x4.trans.shared.b16 {%0,%1,%2,%3}, [%4];"
        : "=r"(r[0]), "=r"(r[1]), "=r"(r[2]), "=r"(r[3]) : "r"(a));
}

__device__ __forceinline__ void mma16816(float* d, const uint32_t* a, const uint32_t* b) {
    asm volatile("mma.sync.aligned.m16n8k16.row.col.f32.f16.f16.f32 "
        "{%0,%1,%2,%3}, {%4,%5,%6,%7}, {%8,%9}, {%0,%1,%2,%3};"
        : "+f"(d[0]), "+f"(d[1]), "+f"(d[2]), "+f"(d[3])
        : "r"(a[0]), "r"(a[1]), "r"(a[2]), "r"(a[3]), "r"(b[0]), "r"(b[1]));
}

// ---------------- activations ----------------
__device__ __forceinline__ float sigf(float v) {
    float e, r;
    asm("ex2.approx.f32 %0, %1;" : "=f"(e) : "f"(-1.4426950408889634f * v));
    asm("rcp.approx.f32 %0, %1;" : "=f"(r) : "f"(1.0f + e));
    return r;
}
__device__ __forceinline__ float tanhf1(float v) {
    float y; asm("tanh.approx.f32 %0, %1;" : "=f"(y) : "f"(v)); return y;
}
__device__ __forceinline__ __half2 sig_h2(__half2 v) {
    const __half2 h05 = __half2half2(__float2half_rn(0.5f));
    __half2 xh = __hmul2(v, h05);
    uint32_t t;
    asm("tanh.approx.f16x2 %0, %1;" : "=r"(t) : "r"(*(uint32_t*)&xh));
    return __hfma2(*(__half2*)&t, h05, h05);
}
__device__ __forceinline__ uint32_t h2u(__half2 h) { return *(uint32_t*)&h; }
__device__ __forceinline__ __half2 u2h(uint32_t u) { return *(__half2*)&u; }

// ============================================================================
// prep kernel: fp16 B images. img[G][k][n], stride 136 halves.
// gate order per layer: Z, G, R, H. k<128: W[L][k][n]; 128..135: U; 136: b.
// ============================================================================
__global__ void prep_kernel(
    const float* __restrict__ Uz, const float* __restrict__ Wz, const float* __restrict__ bz,
    const float* __restrict__ Ug, const float* __restrict__ Wg, const float* __restrict__ bg,
    const float* __restrict__ Ur, const float* __restrict__ Wr, const float* __restrict__ br,
    const float* __restrict__ Uh, const float* __restrict__ Wh, const float* __restrict__ bh)
{
    int t = blockIdx.x * blockDim.x + threadIdx.x;
    if (t >= 12 * GATE_HALVES) return;
    int G = t / GATE_HALVES;
    int rem = t % GATE_HALVES;
    int k = rem / 136;
    int n = rem % 136;
    int L = G >> 2, g = G & 3;
    float val = 0.0f;
    if (n < 128) {
        const float* W = (g == 0) ? Wz : (g == 1) ? Wg : (g == 2) ? Wr : Wh;
        const float* U = (g == 0) ? Uz : (g == 1) ? Ug : (g == 2) ? Ur : Uh;
        const float* bb = (g == 0) ? bz : (g == 1) ? bg : (g == 2) ? br : bh;
        if (k < 128)       val = W[L * 16384 + k * 128 + n];
        else if (k < 136)  val = U[L * 1024 + (k - 128) * 128 + n];
        else if (k == 136) val = bb[L * 128 + n];
    }
    *reinterpret_cast<__half*>(g_wimg + (size_t)G * GATE_BYTES + (size_t)k * 272 + (size_t)n * 2)
        = __float2half_rn(val);
}

// ============================================================================
// main fused kernel: 296 persistent CTAs x 256 threads, 2 CTAs/SM
// ============================================================================
__global__ void __launch_bounds__(256, 2)
dgm_kernel(const float* __restrict__ x,
           const float* __restrict__ Sw_w, const float* __restrict__ Sw_b,
           const float* __restrict__ Wf_w, const float* __restrict__ Wf_b,
           float* __restrict__ out)
{
    extern __shared__ __align__(1024) char smem[];
    const uint32_t sb = smem_to_u32(smem);
    const int tid  = threadIdx.x;
    const int lane = tid & 31;
    const int wid  = tid >> 5;
    const int mgrp = wid & 1;
    const int m0 = mgrp * 32;
    const int n0 = (wid >> 1) * 32;

    float* outs = (float*)(smem + OFF_OUTS);
    float* wf   = (float*)(smem + OFF_WF);
    float* sw   = (float*)(smem + OFF_SW);
    float* swb  = (float*)(smem + OFF_SWB);

    // tiles for this CTA: blockIdx.x, +296, +592, ...
    const int T = (NTILES - (int)blockIdx.x + NCTA - 1) / NCTA;
    const int lastGate = 12 * T;

    if (tid == 0) {
        MBARRIER_INIT(sb + OFF_MBAR,     1);
        MBARRIER_INIT(sb + OFF_MBAR + 8, 1);
        MBARRIER_INIT(sb + OFF_CONS,     8);   // one arrive per warp
        MBARRIER_INIT(sb + OFF_CONS + 8, 8);
        wf[128] = Wf_b[0];
    }
    if (tid < 128) { wf[tid] = Wf_w[tid]; swb[tid] = Sw_b[tid]; }
    if (tid < 64)  outs[tid] = 0.0f;
    ((float4*)sw)[tid] = ((const float4*)Sw_w)[tid];   // 4KB
    __syncthreads();

    // kick first two gate-weight loads (once per CTA, persist across tiles)
    if (tid == 0) {
        MBARRIER_EXPECT_TX(sb + OFF_MBAR, GATE_BYTES);
        bulk_g2s(sb + OFF_SLOT0, g_wimg, GATE_BYTES, sb + OFF_MBAR);
        MBARRIER_EXPECT_TX(sb + OFF_MBAR + 8, GATE_BYTES);
        bulk_g2s(sb + OFF_SLOT1, g_wimg + GATE_BYTES, GATE_BYTES, sb + OFF_MBAR + 8);
    }

    // per-lane ldmatrix address bases (tile-invariant)
    const uint32_t aAddr = sb + OFF_A + (uint32_t)(m0 + (lane & 15)) * 304u
                         + (uint32_t)(lane >> 4) * 16u;
    const uint32_t bOff = (uint32_t)(lane & 15) * 272u
                        + (uint32_t)(n0 + (lane >> 4) * 8) * 2u;

#pragma unroll 1
    for (int t = 0; t < T; t++) {
        const int tile = (int)blockIdx.x + NCTA * t;

        // ---------- S0 = sigmoid(x @ Sw + Sw_b), write A tile + ext ----------
        // r = tid&63, ch = tid>>6: warp-uniform ch -> sw/swb LDS broadcasts,
        // x loads lane-consecutive (R13).
        {
            const int r  = tid & 63;
            const int ch = tid >> 6;
            const float* xr = x + ((size_t)tile * 64 + r) * 8;
            float4 xa = *(const float4*)xr;
            float4 xb = *(const float4*)(xr + 4);
            char* arow = smem + OFF_A + (size_t)r * 304;
            if (ch == 0) {
                *(__half2*)(arow + (128 + 0)  * 2) = __floats2half2_rn(xa.x, xa.y);
                *(__half2*)(arow + (128 + 2)  * 2) = __floats2half2_rn(xa.z, xa.w);
                *(__half2*)(arow + (128 + 4)  * 2) = __floats2half2_rn(xb.x, xb.y);
                *(__half2*)(arow + (128 + 6)  * 2) = __floats2half2_rn(xb.z, xb.w);
                *(__half2*)(arow + (128 + 8)  * 2) = __floats2half2_rn(1.0f, 0.0f);
                *(__half2*)(arow + (128 + 10) * 2) = __floats2half2_rn(0.0f, 0.0f);
                *(__half2*)(arow + (128 + 12) * 2) = __floats2half2_rn(0.0f, 0.0f);
                *(__half2*)(arow + (128 + 14) * 2) = __floats2half2_rn(0.0f, 0.0f);
            }
#pragma unroll 4
            for (int i = 0; i < 16; i++) {
                int c = ch * 32 + 2 * i;
                float s0 = swb[c], s1 = swb[c + 1];
                s0 += xa.x * sw[0 * 128 + c] + xa.y * sw[1 * 128 + c]
                    + xa.z * sw[2 * 128 + c] + xa.w * sw[3 * 128 + c]
                    + xb.x * sw[4 * 128 + c] + xb.y * sw[5 * 128 + c]
                    + xb.z * sw[6 * 128 + c] + xb.w * sw[7 * 128 + c];
                s1 += xa.x * sw[0 * 128 + c + 1] + xa.y * sw[1 * 128 + c + 1]
                    + xa.z * sw[2 * 128 + c + 1] + xa.w * sw[3 * 128 + c + 1]
                    + xb.x * sw[4 * 128 + c + 1] + xb.y * sw[5 * 128 + c + 1]
                    + xb.z * sw[6 * 128 + c + 1] + xb.w * sw[7 * 128 + c + 1];
                *(__half2*)(arow + c * 2) = __floats2half2_rn(sigf(s0), sigf(s1));
            }
        }
        __syncthreads();

        // register stage buffers: [mt*4+nt]
        uint32_t zstA[8], zstB[8], gstA[8], gstB[8];
        float pOut[2][2] = {{0.f, 0.f}, {0.f, 0.f}};

#pragma unroll 1
        for (int G = 0; G < 12; G++) {
            const int g = G & 3;
            const int L = G >> 2;
            const int slot = G & 1;                 // 12 gates/tile: tile-periodic
            const uint32_t slotB = sb + (slot ? OFF_SLOT1 : OFF_SLOT0);
            const int par = (G >> 1) & 1;           // parity also tile-periodic

            MBARRIER_WAIT_PARITY(sb + OFF_MBAR + slot * 8, par);

            float acc[2][4][4];
#pragma unroll
            for (int i = 0; i < 2; i++)
#pragma unroll
                for (int j = 0; j < 4; j++)
#pragma unroll
                    for (int v = 0; v < 4; v++) acc[i][j][v] = 0.0f;

#pragma unroll
            for (int ks = 0; ks < 9; ks++) {
                uint32_t a0[4], a1[4];
                ldsm4(a0, aAddr + (uint32_t)ks * 32u);
                ldsm4(a1, aAddr + 16u * 304u + (uint32_t)ks * 32u);
#pragma unroll
                for (int p = 0; p < 2; p++) {
                    uint32_t b[4];
                    ldsm4t(b, slotB + bOff + (uint32_t)ks * 4352u + (uint32_t)p * 32u);
                    mma16816(acc[0][2 * p],     a0, b);
                    mma16816(acc[0][2 * p + 1], a0, b + 2);
                    mma16816(acc[1][2 * p],     a1, b);
                    mma16816(acc[1][2 * p + 1], a1, b + 2);
                }
            }

            // slot consumed by this warp
            __syncwarp();
            if (lane == 0) MBARRIER_ARRIVE(sb + OFF_CONS + slot * 8);

            // producer: refill with global gate t*12+G+2 (mod 12 image)
            const int nxt = t * 12 + G + 2;
            if (tid == 0 && nxt < lastGate) {
                MBARRIER_WAIT_PARITY(sb + OFF_CONS + slot * 8, par);
                MBARRIER_EXPECT_TX(sb + OFF_MBAR + slot * 8, GATE_BYTES);
                bulk_g2s(slotB, g_wimg + (size_t)((G + 2) % 12) * GATE_BYTES,
                         GATE_BYTES, sb + OFF_MBAR + slot * 8);
            }

            // ---------------- per-gate epilogue ----------------
            if (g == 0) {
                // zst = sig(Z) * sigS  (reads A only)
#pragma unroll
                for (int mt = 0; mt < 2; mt++) {
#pragma unroll
                    for (int nt = 0; nt < 4; nt++) {
                        float* a4 = acc[mt][nt];
                        const int idx  = mt * 4 + nt;
                        const int rowA = m0 + mt * 16 + (lane >> 2);
                        const int col  = n0 + nt * 8 + (lane & 3) * 2;
                        char* aA = smem + OFF_A + (size_t)rowA * 304 + (size_t)col * 2;
                        char* aB = aA + 8 * 304;
                        __half2 sA = *(__half2*)aA, sB = *(__half2*)aB;
                        zstA[idx] = h2u(__hmul2(sig_h2(__floats2half2_rn(a4[0], a4[1])), sA));
                        zstB[idx] = h2u(__hmul2(sig_h2(__floats2half2_rn(a4[2], a4[3])), sB));
                    }
                }
            } else if (g == 1) {
                // gst = sig(G)  (register-only)
#pragma unroll
                for (int mt = 0; mt < 2; mt++) {
#pragma unroll
                    for (int nt = 0; nt < 4; nt++) {
                        float* a4 = acc[mt][nt];
                        const int idx = mt * 4 + nt;
                        gstA[idx] = h2u(sig_h2(__floats2half2_rn(a4[0], a4[1])));
                        gstB[idx] = h2u(sig_h2(__floats2half2_rn(a4[2], a4[3])));
                    }
                }
            } else if (g == 2) {
                // A <- sigS * sig(R): sig(R) precomputed before the barrier
                __half2 rA[8], rB[8];
#pragma unroll
                for (int mt = 0; mt < 2; mt++) {
#pragma unroll
                    for (int nt = 0; nt < 4; nt++) {
                        float* a4 = acc[mt][nt];
                        const int idx = mt * 4 + nt;
                        rA[idx] = sig_h2(__floats2half2_rn(a4[0], a4[1]));
                        rB[idx] = sig_h2(__floats2half2_rn(a4[2], a4[3]));
                    }
                }
                GROUP_BAR(mgrp);
#pragma unroll
                for (int mt = 0; mt < 2; mt++) {
#pragma unroll
                    for (int nt = 0; nt < 4; nt++) {
                        const int idx  = mt * 4 + nt;
                        const int rowA = m0 + mt * 16 + (lane >> 2);
                        const int col  = n0 + nt * 8 + (lane & 3) * 2;
                        char* aA = smem + OFF_A + (size_t)rowA * 304 + (size_t)col * 2;
                        char* aB = aA + 8 * 304;
                        *(__half2*)aA = __hmul2(rA[idx], *(__half2*)aA);
                        *(__half2*)aB = __hmul2(rB[idx], *(__half2*)aB);
                    }
                }
                GROUP_BAR(mgrp);
            } else if (L < 2) {
                // S' epilogue, register work above the barrier
                __half2 oA[8], oB[8];
#pragma unroll
                for (int mt = 0; mt < 2; mt++) {
#pragma unroll
                    for (int nt = 0; nt < 4; nt++) {
                        float* a4 = acc[mt][nt];
                        const int idx = mt * 4 + nt;
                        __half2 zzA = u2h(zstA[idx]), zzB = u2h(zstB[idx]);
                        __half2 ggA = u2h(gstA[idx]), ggB = u2h(gstB[idx]);
                        float sp0 = (1.0f - __low2float(ggA))  * tanhf1(a4[0]) + __low2float(zzA);
                        float sp1 = (1.0f - __high2float(ggA)) * tanhf1(a4[1]) + __high2float(zzA);
                        float sp2 = (1.0f - __low2float(ggB))  * tanhf1(a4[2]) + __low2float(zzB);
                        float sp3 = (1.0f - __high2float(ggB)) * tanhf1(a4[3]) + __high2float(zzB);
                        oA[idx] = sig_h2(__floats2half2_rn(sp0, sp1));
                        oB[idx] = sig_h2(__floats2half2_rn(sp2, sp3));
                    }
                }
                GROUP_BAR(mgrp);
#pragma unroll
                for (int mt = 0; mt < 2; mt++) {
#pragma unroll
                    for (int nt = 0; nt < 4; nt++) {
                        const int idx  = mt * 4 + nt;
                        const int rowA = m0 + mt * 16 + (lane >> 2);
                        const int col  = n0 + nt * 8 + (lane & 3) * 2;
                        char* aA = smem + OFF_A + (size_t)rowA * 304 + (size_t)col * 2;
                        *(__half2*)aA = oA[idx];
                        *(__half2*)(aA + 8 * 304) = oB[idx];
                    }
                }
                GROUP_BAR(mgrp);
            } else {
                // last layer: fold into output dot product (no A writes)
#pragma unroll
                for (int mt = 0; mt < 2; mt++) {
#pragma unroll
                    for (int nt = 0; nt < 4; nt++) {
                        float* a4 = acc[mt][nt];
                        const int idx = mt * 4 + nt;
                        const int col = n0 + nt * 8 + (lane & 3) * 2;
                        __half2 zzA = u2h(zstA[idx]), zzB = u2h(zstB[idx]);
                        __half2 ggA = u2h(gstA[idx]), ggB = u2h(gstB[idx]);
                        float sp0 = (1.0f - __low2float(ggA))  * tanhf1(a4[0]) + __low2float(zzA);
                        float sp1 = (1.0f - __high2float(ggA)) * tanhf1(a4[1]) + __high2float(zzA);
                        float sp2 = (1.0f - __low2float(ggB))  * tanhf1(a4[2]) + __low2float(zzB);
                        float sp3 = (1.0f - __high2float(ggB)) * tanhf1(a4[3]) + __high2float(zzB);
                        pOut[mt][0] += sp0 * wf[col] + sp1 * wf[col + 1];
                        pOut[mt][1] += sp2 * wf[col] + sp3 * wf[col + 1];
                    }
                }
            }
        }

        // ---------------- per-tile reduction: out = S' @ Wf + b ----------------
#pragma unroll
        for (int mt = 0; mt < 2; mt++) {
#pragma unroll
            for (int ab = 0; ab < 2; ab++) {
                float v = pOut[mt][ab];
                v += __shfl_xor_sync(0xffffffffu, v, 1);
                v += __shfl_xor_sync(0xffffffffu, v, 2);
                if ((lane & 3) == 0) {
                    int row = m0 + mt * 16 + (lane >> 2) + ab * 8;
                    atomicAdd(outs + row, v);
                }
            }
        }
        __syncthreads();   // also orders last-gate A reads before next S0 write
        if (tid < 64) {
            out[(size_t)tile * 64 + tid] = outs[tid] + wf[128];
            outs[tid] = 0.0f;   // same thread resets; next adds are far away
        }
    }

    if (tid == 0) {
        mbarrier_inval(sb + OFF_MBAR);
        mbarrier_inval(sb + OFF_MBAR + 8);
        mbarrier_inval(sb + OFF_CONS);
        mbarrier_inval(sb + OFF_CONS + 8);
    }
}

// ============================================================================
extern "C" void kernel_launch(void* const* d_in, const int* in_sizes, int n_in,
                              void* d_out, int out_size) {
    (void)in_sizes; (void)n_in; (void)out_size;
    const float* x     = (const float*)d_in[0];
    const float* Sw_w  = (const float*)d_in[1];
    const float* Sw_b  = (const float*)d_in[2];
    const float* Uz    = (const float*)d_in[3];
    const float* Wsz_w = (const float*)d_in[4];
    const float* Wsz_b = (const float*)d_in[5];
    const float* Ug    = (const float*)d_in[6];
    const float* Wsg_w = (const float*)d_in[7];
    const float* Wsg_b = (const float*)d_in[8];
    const float* Ur    = (const float*)d_in[9];
    const float* Wsr_w = (const float*)d_in[10];
    const float* Wsr_b = (const float*)d_in[11];
    const float* Uh    = (const float*)d_in[12];
    const float* Wsh_w = (const float*)d_in[13];
    const float* Wsh_b = (const float*)d_in[14];
    const float* Wf_w  = (const float*)d_in[15];
    const float* Wf_b  = (const float*)d_in[16];
    float* out = (float*)d_out;

    cudaFuncSetAttribute(dgm_kernel, cudaFuncAttributeMaxDynamicSharedMemorySize,
                         SMEM_TOTAL);

    prep_kernel<<<918, 256>>>(Uz, Wsz_w, Wsz_b, Ug, Wsg_w, Wsg_b,
                              Ur, Wsr_w, Wsr_b, Uh, Wsh_w, Wsh_b);
    dgm_kernel<<<NCTA, 256, SMEM_TOTAL>>>(x, Sw_w, Sw_b, Wf_w, Wf_b, out);
}

// round 17
// speedup vs baseline: 1.0630x; 1.0630x over previous
#include <cuda_runtime.h>
#include <cuda_fp16.h>
#include <cstdint>

// ============================================================================
// DGM cell fused kernel for plain sm_103 (no tcgen05 on this ptxas target).
// mma.sync.m16n8k16 (HMMA) + ldmatrix + cp.async.bulk.
// B=262144, D_IN=8, H=128, N_LAYERS=3, D_OUT=1.
//
// R17 = R14 (339.9us best; R15 atomic-recycle and R16 persistent-CTA both
// regressed and are reverted) + ONE delta: accumulator zero-init removed.
//  * ks=0 peeled and issued with a zero-C MMA (C = 0.0f -> RZ in SASS):
//    kills 32 MOVs per gate per thread (~15% of gate-loop instructions).
//    Arithmetic bit-identical (0 + x = x).
//
// CTA: 64 rows, 256 threads (8 warps). Warp w: rows m0=(w&1)*32,
// cols n0=(w>>1)*32. acc = 2x4 m16n8 tiles (32 fp32 regs).
// A tile (SMEM): [64 rows][152 halves]: sigS 0..127, x 128..135, 1 @136,
// 0 @137..143. Gate = one K=144 MMA chain (x@U + bias folded in).
// B images: [144][136] fp16 per gate, 2-slot ring, prefetch depth 2,
// consumed-mbarrier recycling, m-group named barriers, slimmed critical
// sections (R14), broadcast S0 prologue (R13), f16x2 activations (R8/R11).
// ============================================================================

#define GATE_HALVES (144 * 136)
#define GATE_BYTES  39168u
#define IMG_TOTAL   (12u * GATE_BYTES)

__device__ __align__(1024) unsigned char g_wimg[IMG_TOTAL];

// ---------------- smem layout (bytes) ----------------
#define OFF_MBAR  0u        // 2 full mbarriers
#define OFF_CONS  16u       // 2 consumed mbarriers
#define OFF_OUTS  64u       // 64 f32
#define OFF_WF    320u      // 129 f32 (Wf + bias)
#define OFF_SW    896u      // 8*128 f32
#define OFF_SWB   4992u     // 128 f32
#define OFF_A     5504u     // 64*304 B = 19456 (stride 152 halves)
#define OFF_SLOT0 25600u    // 39168
#define OFF_SLOT1 64768u    // 39168
#define SMEM_TOTAL 103936u

// ---------------- PTX helpers ----------------
__device__ __forceinline__ uint32_t smem_to_u32(const void* p) {
    uint32_t a;
    asm("{ .reg .u64 t; cvta.to.shared.u64 t, %1; cvt.u32.u64 %0, t; }" : "=r"(a) : "l"(p));
    return a;
}

#define MBARRIER_INIT(addr, cnt) \
    asm volatile("mbarrier.init.shared.b64 [%0], %1;" :: "r"((uint32_t)(addr)), "r"((uint32_t)(cnt)) : "memory")

#define MBARRIER_EXPECT_TX(addr, bytes) \
    asm volatile("mbarrier.arrive.expect_tx.shared.b64 _, [%0], %1;" \
        :: "r"((uint32_t)(addr)), "r"((uint32_t)(bytes)) : "memory")

#define MBARRIER_ARRIVE(addr) \
    asm volatile("mbarrier.arrive.shared.b64 _, [%0];" :: "r"((uint32_t)(addr)) : "memory")

#define MBARRIER_WAIT_PARITY(mbar_smem_addr, phase_parity) do { \
    uint32_t _mbar = (uint32_t)(mbar_smem_addr); \
    uint32_t _parity = (uint32_t)(phase_parity); \
    uint32_t _done; \
    asm volatile("{\n\t.reg .pred p;\n\t" \
        "mbarrier.try_wait.parity.acquire.cta.shared::cta.b64 p, [%1], %2;\n\t" \
        "selp.b32 %0, 1, 0, p;\n\t}" \
        : "=r"(_done) : "r"(_mbar), "r"(_parity) : "memory"); \
    if (!_done) { \
        asm volatile("{\n\t.reg .pred P1;\n\t" \
            "WAIT_LOOP_%=:\n\t" \
            "mbarrier.try_wait.parity.acquire.cta.shared::cta.b64 P1, [%0], %1, 0x989680;\n\t" \
            "@P1 bra.uni WAIT_DONE_%=;\n\t" \
            "bra.uni WAIT_LOOP_%=;\n\t" \
            "WAIT_DONE_%=:\n\t}" \
            :: "r"(_mbar), "r"(_parity) : "memory"); \
    } \
} while(0)

__device__ __forceinline__ void mbarrier_inval(uint32_t a) {
    asm volatile("mbarrier.inval.shared.b64 [%0];" :: "r"(a) : "memory");
}

__device__ __forceinline__ void bulk_g2s(uint32_t dst, const void* src,
                                         uint32_t bytes, uint32_t mbar) {
    asm volatile(
        "cp.async.bulk.shared::cluster.global.mbarrier::complete_tx::bytes "
        "[%0], [%1], %2, [%3];"
        :: "r"(dst), "l"(src), "r"(bytes), "r"(mbar) : "memory");
}

// half-CTA barrier for one m-group (4 warps = 128 threads), ids 1 and 2
#define GROUP_BAR(grp) \
    asm volatile("bar.sync %0, %1;" :: "r"((grp) + 1), "r"(128) : "memory")

__device__ __forceinline__ void ldsm4(uint32_t* r, uint32_t a) {
    asm volatile("ldmatrix.sync.aligned.m8n8.x4.shared.b16 {%0,%1,%2,%3}, [%4];"
        : "=r"(r[0]), "=r"(r[1]), "=r"(r[2]), "=r"(r[3]) : "r"(a));
}
__device__ __forceinline__ void ldsm4t(uint32_t* r, uint32_t a) {
    asm volatile("ldmatrix.sync.aligned.m8n8.x4.trans.shared.b16 {%0,%1,%2,%3}, [%4];"
        : "=r"(r[0]), "=r"(r[1]), "=r"(r[2]), "=r"(r[3]) : "r"(a));
}

__device__ __forceinline__ void mma16816(float* d, const uint32_t* a, const uint32_t* b) {
    asm volatile("mma.sync.aligned.m16n8k16.row.col.f32.f16.f16.f32 "
        "{%0,%1,%2,%3}, {%4,%5,%6,%7}, {%8,%9}, {%0,%1,%2,%3};"
        : "+f"(d[0]), "+f"(d[1]), "+f"(d[2]), "+f"(d[3])
        : "r"(a[0]), "r"(a[1]), "r"(a[2]), "r"(a[3]), "r"(b[0]), "r"(b[1]));
}

// zero-C MMA: D = A*B + 0 (C operands are 0.0f -> RZ); replaces acc zero-init
__device__ __forceinline__ void mma16816_z(float* d, const uint32_t* a, const uint32_t* b) {
    asm volatile("mma.sync.aligned.m16n8k16.row.col.f32.f16.f16.f32 "
        "{%0,%1,%2,%3}, {%4,%5,%6,%7}, {%8,%9}, {%10,%11,%12,%13};"
        : "=f"(d[0]), "=f"(d[1]), "=f"(d[2]), "=f"(d[3])
        : "r"(a[0]), "r"(a[1]), "r"(a[2]), "r"(a[3]), "r"(b[0]), "r"(b[1]),
          "f"(0.0f), "f"(0.0f), "f"(0.0f), "f"(0.0f));
}

// ---------------- activations ----------------
__device__ __forceinline__ float sigf(float v) {
    float e, r;
    asm("ex2.approx.f32 %0, %1;" : "=f"(e) : "f"(-1.4426950408889634f * v));
    asm("rcp.approx.f32 %0, %1;" : "=f"(r) : "f"(1.0f + e));
    return r;
}
__device__ __forceinline__ float tanhf1(float v) {
    float y; asm("tanh.approx.f32 %0, %1;" : "=f"(y) : "f"(v)); return y;
}
__device__ __forceinline__ __half2 sig_h2(__half2 v) {
    const __half2 h05 = __half2half2(__float2half_rn(0.5f));
    __half2 xh = __hmul2(v, h05);
    uint32_t t;
    asm("tanh.approx.f16x2 %0, %1;" : "=r"(t) : "r"(*(uint32_t*)&xh));
    return __hfma2(*(__half2*)&t, h05, h05);
}
__device__ __forceinline__ uint32_t h2u(__half2 h) { return *(uint32_t*)&h; }
__device__ __forceinline__ __half2 u2h(uint32_t u) { return *(__half2*)&u; }

// ============================================================================
// prep kernel: fp16 B images. img[G][k][n], stride 136 halves.
// gate order per layer: Z, G, R, H. k<128: W[L][k][n]; 128..135: U; 136: b.
// ============================================================================
__global__ void prep_kernel(
    const float* __restrict__ Uz, const float* __restrict__ Wz, const float* __restrict__ bz,
    const float* __restrict__ Ug, const float* __restrict__ Wg, const float* __restrict__ bg,
    const float* __restrict__ Ur, const float* __restrict__ Wr, const float* __restrict__ br,
    const float* __restrict__ Uh, const float* __restrict__ Wh, const float* __restrict__ bh)
{
    int t = blockIdx.x * blockDim.x + threadIdx.x;
    if (t >= 12 * GATE_HALVES) return;
    int G = t / GATE_HALVES;
    int rem = t % GATE_HALVES;
    int k = rem / 136;
    int n = rem % 136;
    int L = G >> 2, g = G & 3;
    float val = 0.0f;
    if (n < 128) {
        const float* W = (g == 0) ? Wz : (g == 1) ? Wg : (g == 2) ? Wr : Wh;
        const float* U = (g == 0) ? Uz : (g == 1) ? Ug : (g == 2) ? Ur : Uh;
        const float* bb = (g == 0) ? bz : (g == 1) ? bg : (g == 2) ? br : bh;
        if (k < 128)       val = W[L * 16384 + k * 128 + n];
        else if (k < 136)  val = U[L * 1024 + (k - 128) * 128 + n];
        else if (k == 136) val = bb[L * 128 + n];
    }
    *reinterpret_cast<__half*>(g_wimg + (size_t)G * GATE_BYTES + (size_t)k * 272 + (size_t)n * 2)
        = __float2half_rn(val);
}

// ============================================================================
// main fused kernel: 4096 CTAs x 256 threads, 2 CTAs/SM
// ============================================================================
__global__ void __launch_bounds__(256, 2)
dgm_kernel(const float* __restrict__ x,
           const float* __restrict__ Sw_w, const float* __restrict__ Sw_b,
           const float* __restrict__ Wf_w, const float* __restrict__ Wf_b,
           float* __restrict__ out)
{
    extern __shared__ __align__(1024) char smem[];
    const uint32_t sb = smem_to_u32(smem);
    const int tid  = threadIdx.x;
    const int lane = tid & 31;
    const int wid  = tid >> 5;
    const int mgrp = wid & 1;
    const int m0 = mgrp * 32;
    const int n0 = (wid >> 1) * 32;

    float* outs = (float*)(smem + OFF_OUTS);
    float* wf   = (float*)(smem + OFF_WF);
    float* sw   = (float*)(smem + OFF_SW);
    float* swb  = (float*)(smem + OFF_SWB);

    if (tid == 0) {
        MBARRIER_INIT(sb + OFF_MBAR,     1);
        MBARRIER_INIT(sb + OFF_MBAR + 8, 1);
        MBARRIER_INIT(sb + OFF_CONS,     8);   // one arrive per warp
        MBARRIER_INIT(sb + OFF_CONS + 8, 8);
        wf[128] = Wf_b[0];
    }
    if (tid < 128) { wf[tid] = Wf_w[tid]; swb[tid] = Sw_b[tid]; }
    if (tid < 64)  outs[tid] = 0.0f;
    ((float4*)sw)[tid] = ((const float4*)Sw_w)[tid];   // 4KB
    __syncthreads();

    // kick first two gate-weight loads
    if (tid == 0) {
        MBARRIER_EXPECT_TX(sb + OFF_MBAR, GATE_BYTES);
        bulk_g2s(sb + OFF_SLOT0, g_wimg, GATE_BYTES, sb + OFF_MBAR);
        MBARRIER_EXPECT_TX(sb + OFF_MBAR + 8, GATE_BYTES);
        bulk_g2s(sb + OFF_SLOT1, g_wimg + GATE_BYTES, GATE_BYTES, sb + OFF_MBAR + 8);
    }

    // ---------- S0 = sigmoid(x @ Sw + Sw_b), write A tile + ext ----------
    // r = tid&63, ch = tid>>6: warp-uniform ch -> sw/swb LDS broadcasts,
    // x loads lane-consecutive (R13, the 100us win).
    {
        const int r  = tid & 63;
        const int ch = tid >> 6;
        const float* xr = x + ((size_t)blockIdx.x * 64 + r) * 8;
        float4 xa = *(const float4*)xr;
        float4 xb = *(const float4*)(xr + 4);
        char* arow = smem + OFF_A + (size_t)r * 304;
        if (ch == 0) {
            *(__half2*)(arow + (128 + 0)  * 2) = __floats2half2_rn(xa.x, xa.y);
            *(__half2*)(arow + (128 + 2)  * 2) = __floats2half2_rn(xa.z, xa.w);
            *(__half2*)(arow + (128 + 4)  * 2) = __floats2half2_rn(xb.x, xb.y);
            *(__half2*)(arow + (128 + 6)  * 2) = __floats2half2_rn(xb.z, xb.w);
            *(__half2*)(arow + (128 + 8)  * 2) = __floats2half2_rn(1.0f, 0.0f);
            *(__half2*)(arow + (128 + 10) * 2) = __floats2half2_rn(0.0f, 0.0f);
            *(__half2*)(arow + (128 + 12) * 2) = __floats2half2_rn(0.0f, 0.0f);
            *(__half2*)(arow + (128 + 14) * 2) = __floats2half2_rn(0.0f, 0.0f);
        }
#pragma unroll 4
        for (int i = 0; i < 16; i++) {
            int c = ch * 32 + 2 * i;
            float s0 = swb[c], s1 = swb[c + 1];
            s0 += xa.x * sw[0 * 128 + c] + xa.y * sw[1 * 128 + c]
                + xa.z * sw[2 * 128 + c] + xa.w * sw[3 * 128 + c]
                + xb.x * sw[4 * 128 + c] + xb.y * sw[5 * 128 + c]
                + xb.z * sw[6 * 128 + c] + xb.w * sw[7 * 128 + c];
            s1 += xa.x * sw[0 * 128 + c + 1] + xa.y * sw[1 * 128 + c + 1]
                + xa.z * sw[2 * 128 + c + 1] + xa.w * sw[3 * 128 + c + 1]
                + xb.x * sw[4 * 128 + c + 1] + xb.y * sw[5 * 128 + c + 1]
                + xb.z * sw[6 * 128 + c + 1] + xb.w * sw[7 * 128 + c + 1];
            *(__half2*)(arow + c * 2) = __floats2half2_rn(sigf(s0), sigf(s1));
        }
    }
    __syncthreads();

    // per-lane ldmatrix address bases
    const uint32_t aAddr = sb + OFF_A + (uint32_t)(m0 + (lane & 15)) * 304u
                         + (uint32_t)(lane >> 4) * 16u;
    const uint32_t bOff = (uint32_t)(lane & 15) * 272u
                        + (uint32_t)(n0 + (lane >> 4) * 8) * 2u;

    // register stage buffers: [mt*4+nt]
    uint32_t zstA[8], zstB[8], gstA[8], gstB[8];
    float pOut[2][2] = {{0.f, 0.f}, {0.f, 0.f}};

#pragma unroll 1
    for (int G = 0; G < 12; G++) {
        const int g = G & 3;
        const int L = G >> 2;
        const int slot = G & 1;
        const uint32_t slotB = sb + (slot ? OFF_SLOT1 : OFF_SLOT0);

        MBARRIER_WAIT_PARITY(sb + OFF_MBAR + slot * 8, (G >> 1) & 1);

        float acc[2][4][4];

        // ks = 0 peeled: zero-C MMA writes acc directly (no zero-init movs)
        {
            uint32_t a0[4], a1[4];
            ldsm4(a0, aAddr);
            ldsm4(a1, aAddr + 16u * 304u);
#pragma unroll
            for (int p = 0; p < 2; p++) {
                uint32_t b[4];
                ldsm4t(b, slotB + bOff + (uint32_t)p * 32u);
                mma16816_z(acc[0][2 * p],     a0, b);
                mma16816_z(acc[0][2 * p + 1], a0, b + 2);
                mma16816_z(acc[1][2 * p],     a1, b);
                mma16816_z(acc[1][2 * p + 1], a1, b + 2);
            }
        }
#pragma unroll
        for (int ks = 1; ks < 9; ks++) {
            uint32_t a0[4], a1[4];
            ldsm4(a0, aAddr + (uint32_t)ks * 32u);
            ldsm4(a1, aAddr + 16u * 304u + (uint32_t)ks * 32u);
#pragma unroll
            for (int p = 0; p < 2; p++) {
                uint32_t b[4];
                ldsm4t(b, slotB + bOff + (uint32_t)ks * 4352u + (uint32_t)p * 32u);
                mma16816(acc[0][2 * p],     a0, b);
                mma16816(acc[0][2 * p + 1], a0, b + 2);
                mma16816(acc[1][2 * p],     a1, b);
                mma16816(acc[1][2 * p + 1], a1, b + 2);
            }
        }

        // slot consumed by this warp
        __syncwarp();
        if (lane == 0) MBARRIER_ARRIVE(sb + OFF_CONS + slot * 8);

        // producer: refill this slot with gate G+2 after all 8 warps consumed
        if (tid == 0 && G < 10) {
            MBARRIER_WAIT_PARITY(sb + OFF_CONS + slot * 8, (G >> 1) & 1);
            MBARRIER_EXPECT_TX(sb + OFF_MBAR + slot * 8, GATE_BYTES);
            bulk_g2s(slotB, g_wimg + (size_t)(G + 2) * GATE_BYTES, GATE_BYTES,
                     sb + OFF_MBAR + slot * 8);
        }

        // ---------------- per-gate epilogue ----------------
        if (g == 0) {
            // zst = sig(Z) * sigS  (reads A only, no barrier needed)
#pragma unroll
            for (int mt = 0; mt < 2; mt++) {
#pragma unroll
                for (int nt = 0; nt < 4; nt++) {
                    float* a4 = acc[mt][nt];
                    const int idx  = mt * 4 + nt;
                    const int rowA = m0 + mt * 16 + (lane >> 2);
                    const int col  = n0 + nt * 8 + (lane & 3) * 2;
                    char* aA = smem + OFF_A + (size_t)rowA * 304 + (size_t)col * 2;
                    char* aB = aA + 8 * 304;
                    __half2 sA = *(__half2*)aA, sB = *(__half2*)aB;
                    zstA[idx] = h2u(__hmul2(sig_h2(__floats2half2_rn(a4[0], a4[1])), sA));
                    zstB[idx] = h2u(__hmul2(sig_h2(__floats2half2_rn(a4[2], a4[3])), sB));
                }
            }
        } else if (g == 1) {
            // gst = sig(G)  (register-only)
#pragma unroll
            for (int mt = 0; mt < 2; mt++) {
#pragma unroll
                for (int nt = 0; nt < 4; nt++) {
                    float* a4 = acc[mt][nt];
                    const int idx = mt * 4 + nt;
                    gstA[idx] = h2u(sig_h2(__floats2half2_rn(a4[0], a4[1])));
                    gstB[idx] = h2u(sig_h2(__floats2half2_rn(a4[2], a4[3])));
                }
            }
        } else if (g == 2) {
            // A <- sigS * sig(R): precompute sig(R) BEFORE the barrier
            __half2 rA[8], rB[8];
#pragma unroll
            for (int mt = 0; mt < 2; mt++) {
#pragma unroll
                for (int nt = 0; nt < 4; nt++) {
                    float* a4 = acc[mt][nt];
                    const int idx = mt * 4 + nt;
                    rA[idx] = sig_h2(__floats2half2_rn(a4[0], a4[1]));
                    rB[idx] = sig_h2(__floats2half2_rn(a4[2], a4[3]));
                }
            }
            GROUP_BAR(mgrp);   // m-group's A reads (MMA) done
#pragma unroll
            for (int mt = 0; mt < 2; mt++) {
#pragma unroll
                for (int nt = 0; nt < 4; nt++) {
                    const int idx  = mt * 4 + nt;
                    const int rowA = m0 + mt * 16 + (lane >> 2);
                    const int col  = n0 + nt * 8 + (lane & 3) * 2;
                    char* aA = smem + OFF_A + (size_t)rowA * 304 + (size_t)col * 2;
                    char* aB = aA + 8 * 304;
                    *(__half2*)aA = __hmul2(rA[idx], *(__half2*)aA);
                    *(__half2*)aB = __hmul2(rB[idx], *(__half2*)aB);
                }
            }
            GROUP_BAR(mgrp);   // A2 visible before H's MMA reads
        } else if (L < 2) {
            // S' = (1-sigG)*tanh(H) + zst, then sigmoid — register work
            // hoisted above the barrier; only stores between bars.
            __half2 oA[8], oB[8];
#pragma unroll
            for (int mt = 0; mt < 2; mt++) {
#pragma unroll
                for (int nt = 0; nt < 4; nt++) {
                    float* a4 = acc[mt][nt];
                    const int idx = mt * 4 + nt;
                    __half2 zzA = u2h(zstA[idx]), zzB = u2h(zstB[idx]);
                    __half2 ggA = u2h(gstA[idx]), ggB = u2h(gstB[idx]);
                    float sp0 = (1.0f - __low2float(ggA))  * tanhf1(a4[0]) + __low2float(zzA);
                    float sp1 = (1.0f - __high2float(ggA)) * tanhf1(a4[1]) + __high2float(zzA);
                    float sp2 = (1.0f - __low2float(ggB))  * tanhf1(a4[2]) + __low2float(zzB);
                    float sp3 = (1.0f - __high2float(ggB)) * tanhf1(a4[3]) + __high2float(zzB);
                    oA[idx] = sig_h2(__floats2half2_rn(sp0, sp1));
                    oB[idx] = sig_h2(__floats2half2_rn(sp2, sp3));
                }
            }
            GROUP_BAR(mgrp);   // m-group's A2 reads (H MMA) done
#pragma unroll
            for (int mt = 0; mt < 2; mt++) {
#pragma unroll
                for (int nt = 0; nt < 4; nt++) {
                    const int idx  = mt * 4 + nt;
                    const int rowA = m0 + mt * 16 + (lane >> 2);
                    const int col  = n0 + nt * 8 + (lane & 3) * 2;
                    char* aA = smem + OFF_A + (size_t)rowA * 304 + (size_t)col * 2;
                    *(__half2*)aA = oA[idx];
                    *(__half2*)(aA + 8 * 304) = oB[idx];
                }
            }
            GROUP_BAR(mgrp);   // S' visible before next layer's MMA reads
        } else {
            // last layer: fold into output dot product (no A writes)
#pragma unroll
            for (int mt = 0; mt < 2; mt++) {
#pragma unroll
                for (int nt = 0; nt < 4; nt++) {
                    float* a4 = acc[mt][nt];
                    const int idx = mt * 4 + nt;
                    const int col = n0 + nt * 8 + (lane & 3) * 2;
                    __half2 zzA = u2h(zstA[idx]), zzB = u2h(zstB[idx]);
                    __half2 ggA = u2h(gstA[idx]), ggB = u2h(gstB[idx]);
                    float sp0 = (1.0f - __low2float(ggA))  * tanhf1(a4[0]) + __low2float(zzA);
                    float sp1 = (1.0f - __high2float(ggA)) * tanhf1(a4[1]) + __high2float(zzA);
                    float sp2 = (1.0f - __low2float(ggB))  * tanhf1(a4[2]) + __low2float(zzB);
                    float sp3 = (1.0f - __high2float(ggB)) * tanhf1(a4[3]) + __high2float(zzB);
                    pOut[mt][0] += sp0 * wf[col] + sp1 * wf[col + 1];
                    pOut[mt][1] += sp2 * wf[col] + sp3 * wf[col + 1];
                }
            }
        }
    }

    // ---------------- final reduction: out = S' @ Wf + b ----------------
#pragma unroll
    for (int mt = 0; mt < 2; mt++) {
#pragma unroll
        for (int ab = 0; ab < 2; ab++) {
            float v = pOut[mt][ab];
            v += __shfl_xor_sync(0xffffffffu, v, 1);
            v += __shfl_xor_sync(0xffffffffu, v, 2);
            if ((lane & 3) == 0) {
                int row = m0 + mt * 16 + (lane >> 2) + ab * 8;
                atomicAdd(outs + row, v);
            }
        }
    }
    __syncthreads();
    if (tid < 64)
        out[(size_t)blockIdx.x * 64 + tid] = outs[tid] + wf[128];

    if (tid == 0) {
        mbarrier_inval(sb + OFF_MBAR);
        mbarrier_inval(sb + OFF_MBAR + 8);
        mbarrier_inval(sb + OFF_CONS);
        mbarrier_inval(sb + OFF_CONS + 8);
    }
}

// ============================================================================
extern "C" void kernel_launch(void* const* d_in, const int* in_sizes, int n_in,
                              void* d_out, int out_size) {
    (void)in_sizes; (void)n_in; (void)out_size;
    const float* x     = (const float*)d_in[0];
    const float* Sw_w  = (const float*)d_in[1];
    const float* Sw_b  = (const float*)d_in[2];
    const float* Uz    = (const float*)d_in[3];
    const float* Wsz_w = (const float*)d_in[4];
    const float* Wsz_b = (const float*)d_in[5];
    const float* Ug    = (const float*)d_in[6];
    const float* Wsg_w = (const float*)d_in[7];
    const float* Wsg_b = (const float*)d_in[8];
    const float* Ur    = (const float*)d_in[9];
    const float* Wsr_w = (const float*)d_in[10];
    const float* Wsr_b = (const float*)d_in[11];
    const float* Uh    = (const float*)d_in[12];
    const float* Wsh_w = (const float*)d_in[13];
    const float* Wsh_b = (const float*)d_in[14];
    const float* Wf_w  = (const float*)d_in[15];
    const float* Wf_b  = (const float*)d_in[16];
    float* out = (float*)d_out;

    cudaFuncSetAttribute(dgm_kernel, cudaFuncAttributeMaxDynamicSharedMemorySize,
                         SMEM_TOTAL);

    prep_kernel<<<918, 256>>>(Uz, Wsz_w, Wsz_b, Ug, Wsg_w, Wsg_b,
                              Ur, Wsr_w, Wsr_b, Uh, Wsh_w, Wsh_b);
    dgm_kernel<<<4096, 256, SMEM_TOTAL>>>(x, Sw_w, Sw_b, Wf_w, Wf_b, out);
}